// round 14
// baseline (speedup 1.0000x reference)
#include <cuda_runtime.h>

#define BSZ 4
#define NH  16
#define TT  2048
#define DD  1024
#define DH  64

// scratch: [3][B][H]... Q: [T][64], K: TRANSPOSED [64][T], V: [T][64]; tf32 bits
static __device__ float g_qkv[(size_t)3 * BSZ * NH * TT * DH];

__device__ __forceinline__ unsigned f2tf(float f) {
    unsigned u;
    asm("cvt.rna.tf32.f32 %0, %1;" : "=r"(u) : "f"(f));
    return u;
}

__device__ __forceinline__ void mma8(float* c,
                                     unsigned a0, unsigned a1, unsigned a2, unsigned a3,
                                     unsigned b0, unsigned b1) {
    asm volatile(
        "mma.sync.aligned.m16n8k8.row.col.f32.tf32.tf32.f32 "
        "{%0,%1,%2,%3},{%4,%5,%6,%7},{%8,%9},{%0,%1,%2,%3};"
        : "+f"(c[0]), "+f"(c[1]), "+f"(c[2]), "+f"(c[3])
        : "r"(a0), "r"(a1), "r"(a2), "r"(a3), "r"(b0), "r"(b1));
}

// column permutation for the 4-nt LDS.128 trick: x = logical col (0..63)
__device__ __forceinline__ int qperm(int x) {
    return ((x >> 3) & 3) | (((x >> 1) & 3) << 2) | ((x & 1) << 4) | ((x >> 5) << 5);
}

// ============================================================================
// Kernel 1: QKV projection + q/k normalization. K written TRANSPOSED [e][t].
// (unchanged — proven)
// ============================================================================
__global__ __launch_bounds__(256, 2) void qkv_proj_kernel(const float* __restrict__ x,
                                                          const float* __restrict__ w) {
    __shared__ unsigned sX[32 * 264];  // [d][t] tf32, pad 8
    __shared__ unsigned sW[32 * 72];   // [d][e] tf32, pad 8

    const int t0  = blockIdx.x * 256;
    const int nbh = blockIdx.y;
    const int n   = nbh >> 6;
    const int b   = (nbh >> 4) & 3;
    const int hh  = nbh & 15;

    const float* xb = x + (size_t)b * DD * TT + t0;
    const float* wb = w + (size_t)(n * NH + hh) * DD * DH;

    const int tid  = threadIdx.x;
    const int lane = tid & 31;
    const int wid  = tid >> 5;
    const int grp  = lane >> 2;
    const int tig  = lane & 3;
    const int rb   = wid * 32;

    float acc[2][8][4];
#pragma unroll
    for (int mt = 0; mt < 2; mt++)
#pragma unroll
        for (int nt = 0; nt < 8; nt++)
            acc[mt][nt][0] = acc[mt][nt][1] = acc[mt][nt][2] = acc[mt][nt][3] = 0.f;

    for (int kt = 0; kt < DD; kt += 32) {
#pragma unroll
        for (int i = 0; i < 8; i++) {
            int idx = i * 256 + tid;
            int dd  = idx >> 6;
            int t4  = idx & 63;
            float4 v = *(const float4*)(xb + (size_t)(kt + dd) * TT + t4 * 4);
            uint4 u = make_uint4(f2tf(v.x), f2tf(v.y), f2tf(v.z), f2tf(v.w));
            *(uint4*)&sX[dd * 264 + t4 * 4] = u;
        }
#pragma unroll
        for (int i = 0; i < 2; i++) {
            int idx = i * 256 + tid;
            int dd  = idx >> 4;
            int e4  = idx & 15;
            float4 v = *(const float4*)(wb + (size_t)(kt + dd) * DH + e4 * 4);
            uint4 u = make_uint4(f2tf(v.x), f2tf(v.y), f2tf(v.z), f2tf(v.w));
            *(uint4*)&sW[dd * 72 + e4 * 4] = u;
        }
        __syncthreads();

#pragma unroll
        for (int ks = 0; ks < 4; ks++) {
            const int k0 = ks * 8;
            unsigned a[2][4];
#pragma unroll
            for (int mt = 0; mt < 2; mt++) {
                const int r = rb + mt * 16 + grp;
                a[mt][0] = sX[(k0 + tig) * 264 + r];
                a[mt][1] = sX[(k0 + tig) * 264 + r + 8];
                a[mt][2] = sX[(k0 + tig + 4) * 264 + r];
                a[mt][3] = sX[(k0 + tig + 4) * 264 + r + 8];
            }
#pragma unroll
            for (int nt = 0; nt < 8; nt++) {
                unsigned b0 = sW[(k0 + tig) * 72 + nt * 8 + grp];
                unsigned b1 = sW[(k0 + tig + 4) * 72 + nt * 8 + grp];
                mma8(acc[0][nt], a[0][0], a[0][1], a[0][2], a[0][3], b0, b1);
                mma8(acc[1][nt], a[1][0], a[1][1], a[1][2], a[1][3], b0, b1);
            }
        }
        __syncthreads();
    }

    if (n < 2) {
#pragma unroll
        for (int mt = 0; mt < 2; mt++) {
            float slo = 0.f, shi = 0.f;
#pragma unroll
            for (int nt = 0; nt < 8; nt++) {
                slo += acc[mt][nt][0] + acc[mt][nt][1];
                shi += acc[mt][nt][2] + acc[mt][nt][3];
            }
            slo += __shfl_xor_sync(~0u, slo, 1); slo += __shfl_xor_sync(~0u, slo, 2);
            shi += __shfl_xor_sync(~0u, shi, 1); shi += __shfl_xor_sync(~0u, shi, 2);
            float mlo = slo * (1.f / 64.f), mhi = shi * (1.f / 64.f);
            float vlo = 0.f, vhi = 0.f;
#pragma unroll
            for (int nt = 0; nt < 8; nt++) {
                float d0 = acc[mt][nt][0] - mlo, d1 = acc[mt][nt][1] - mlo;
                float d2 = acc[mt][nt][2] - mhi, d3 = acc[mt][nt][3] - mhi;
                vlo += d0 * d0 + d1 * d1;
                vhi += d2 * d2 + d3 * d3;
            }
            vlo += __shfl_xor_sync(~0u, vlo, 1); vlo += __shfl_xor_sync(~0u, vlo, 2);
            vhi += __shfl_xor_sync(~0u, vhi, 1); vhi += __shfl_xor_sync(~0u, vhi, 2);
            float ilo = 1.f / (sqrtf(vlo * (1.f / 63.f)) + 1e-5f);
            float ihi = 1.f / (sqrtf(vhi * (1.f / 63.f)) + 1e-5f);
#pragma unroll
            for (int nt = 0; nt < 8; nt++) {
                acc[mt][nt][0] = (acc[mt][nt][0] - mlo) * ilo;
                acc[mt][nt][1] = (acc[mt][nt][1] - mlo) * ilo;
                acc[mt][nt][2] = (acc[mt][nt][2] - mhi) * ihi;
                acc[mt][nt][3] = (acc[mt][nt][3] - mhi) * ihi;
            }
        }
    }

    float* dst = g_qkv + (((size_t)n * BSZ + b) * NH + hh) * (size_t)TT * DH;
    if (n == 1) {
        // K stored TRANSPOSED: [e][t]
#pragma unroll
        for (int mt = 0; mt < 2; mt++) {
            const int rlo = t0 + rb + mt * 16 + grp;
            const int rhi = rlo + 8;
#pragma unroll
            for (int nt = 0; nt < 8; nt++) {
                int e = nt * 8 + 2 * tig;
                dst[(size_t)e * TT + rlo]       = __uint_as_float(f2tf(acc[mt][nt][0]));
                dst[(size_t)(e + 1) * TT + rlo] = __uint_as_float(f2tf(acc[mt][nt][1]));
                dst[(size_t)e * TT + rhi]       = __uint_as_float(f2tf(acc[mt][nt][2]));
                dst[(size_t)(e + 1) * TT + rhi] = __uint_as_float(f2tf(acc[mt][nt][3]));
            }
        }
    } else {
#pragma unroll
        for (int mt = 0; mt < 2; mt++) {
            const int rlo = t0 + rb + mt * 16 + grp;
            const int rhi = rlo + 8;
#pragma unroll
            for (int nt = 0; nt < 8; nt++) {
                int e = nt * 8 + 2 * tig;
                *(float2*)(dst + (size_t)rlo * DH + e) =
                    make_float2(__uint_as_float(f2tf(acc[mt][nt][0])),
                                __uint_as_float(f2tf(acc[mt][nt][1])));
                *(float2*)(dst + (size_t)rhi * DH + e) =
                    make_float2(__uint_as_float(f2tf(acc[mt][nt][2])),
                                __uint_as_float(f2tf(acc[mt][nt][3])));
            }
        }
    }
}

// ============================================================================
// Kernel 2: flash attention, split-warp cooperative tiling.
// grid (T/128, B*H), 256 threads, 2 blocks/SM.
// Warp = (rg = wid&3: 32 q-rows) x (ch = wid>>2: 32 s-cols).
// S: 32x32 (half K tile). PV: warp's 32 s-rows of V x all 64 e (half V tile).
// P is warp-local. O and l partials reduced across the ch-pair at epilogue
// (legal because no-max softmax defers the 1/l to the end).
// ============================================================================
#define SMEM2_WORDS (128 * 68 + 64 * 64 + 64 * 64 + 128 * 64)

__global__ __launch_bounds__(256, 2) void attn_kernel(float* __restrict__ out) {
    extern __shared__ unsigned sm[];
    unsigned* sQ  = sm;                // [128][68]
    unsigned* sKT = sQ + 128 * 68;     // [64][64] permuted+swizzled (l-exchange at epilogue)
    unsigned* sV  = sKT + 64 * 64;     // [64][64] permuted+swizzled
    unsigned* sP  = sV + 64 * 64;      // [128][64] swizzled (O-exchange at epilogue)

    const int t0 = blockIdx.x * 128;
    const int b  = blockIdx.y >> 4;
    const int hh = blockIdx.y & 15;

    const size_t base = (((size_t)b) * NH + hh) * (size_t)TT * DH;
    const size_t pl   = (size_t)BSZ * NH * TT * DH;
    const float* Qg = g_qkv + base;            // [T][64]
    const float* Kg = g_qkv + pl + base;       // TRANSPOSED [64][T]
    const float* Vg = g_qkv + 2 * pl + base;   // [T][64]

    const int tid  = threadIdx.x;
    const int lane = tid & 31;
    const int wid  = tid >> 5;
    const int grp  = lane >> 2;
    const int tig  = lane & 3;
    const int rg   = wid & 3;          // row group: 32 q-rows
    const int ch   = wid >> 2;         // column half: 32 s-cols
    const int rb   = rg * 32;
    const int xp   = ((grp & 3) << 3) | ((grp >> 2) << 2);  // sP swizzle key
    const int pb0  = ((grp >> 1) << 2) | ((grp & 1) << 4);  // nt-block 0 base pos
    const int pb1  = pb0 | 32;                              // nt-block 1
    const int pbS  = pb0 | (ch << 5);                       // warp's S half
    const int xk   = tig << 2;

    // load Q tile once: 128x64 uint4 (already tf32 bits)
    {
        const uint4* Qg4 = (const uint4*)(Qg + (size_t)t0 * DH);
#pragma unroll
        for (int i = 0; i < 8; i++) {
            int idx = i * 256 + tid;
            int r = idx >> 4, e4 = idx & 15;
            *(uint4*)&sQ[r * 68 + e4 * 4] = Qg4[idx];
        }
    }

    float o[2][8][4];
#pragma unroll
    for (int mt = 0; mt < 2; mt++)
#pragma unroll
        for (int nt = 0; nt < 8; nt++)
            o[mt][nt][0] = o[mt][nt][1] = o[mt][nt][2] = o[mt][nt][3] = 0.f;
    float l[2][2] = {{0.f, 0.f}, {0.f, 0.f}};

    for (int s0 = 0; s0 < TT; s0 += 64) {
        // ---- stage K^T tile [d][pos(s)] and V tile [s][pos(e)]
        {
#pragma unroll
            for (int i = 0; i < 4; i++) {
                int idx = i * 256 + tid;
                int d = idx >> 4, s4 = idx & 15;
                uint4 v = *(const uint4*)(Kg + (size_t)d * TT + s0 + s4 * 4);
                unsigned* row = &sKT[d * 64];
                int key = (d & 3) << 2;
                row[qperm(4 * s4 + 0) ^ key] = v.x;
                row[qperm(4 * s4 + 1) ^ key] = v.y;
                row[qperm(4 * s4 + 2) ^ key] = v.z;
                row[qperm(4 * s4 + 3) ^ key] = v.w;
            }
#pragma unroll
            for (int i = 0; i < 4; i++) {
                int idx = i * 256 + tid;
                int sl = idx >> 4, e4 = idx & 15;
                uint4 v = *(const uint4*)(Vg + (size_t)(s0 + sl) * DH + e4 * 4);
                unsigned* row = &sV[sl * 64];
                int key = (sl & 3) << 2;
                row[qperm(4 * e4 + 0) ^ key] = v.x;
                row[qperm(4 * e4 + 1) ^ key] = v.y;
                row[qperm(4 * e4 + 2) ^ key] = v.z;
                row[qperm(4 * e4 + 3) ^ key] = v.w;
            }
        }
        __syncthreads();  // tiles visible (first iter: also covers Q load)

        // ---- S = Q K^T  (32 rows x warp's 32 s-cols)
        float sa[2][4][4];
#pragma unroll
        for (int mt = 0; mt < 2; mt++)
#pragma unroll
            for (int j = 0; j < 4; j++)
                sa[mt][j][0] = sa[mt][j][1] = sa[mt][j][2] = sa[mt][j][3] = 0.f;
#pragma unroll
        for (int ks = 0; ks < 8; ks++) {
            const int k0 = ks * 8;
            unsigned a[2][4];
#pragma unroll
            for (int mt = 0; mt < 2; mt++) {
                const int r = rb + mt * 16 + grp;
                a[mt][0] = sQ[r * 68 + k0 + tig];
                a[mt][1] = sQ[(r + 8) * 68 + k0 + tig];
                a[mt][2] = sQ[r * 68 + k0 + tig + 4];
                a[mt][3] = sQ[(r + 8) * 68 + k0 + tig + 4];
            }
            unsigned kb[2][4];
#pragma unroll
            for (int h = 0; h < 2; h++) {
                int row = k0 + tig + 4 * h;
                *(uint4*)kb[h] = *(const uint4*)&sKT[row * 64 + (pbS ^ xk)];
            }
#pragma unroll
            for (int j = 0; j < 4; j++) {
                mma8(sa[0][j], a[0][0], a[0][1], a[0][2], a[0][3], kb[0][j], kb[1][j]);
                mma8(sa[1][j], a[1][0], a[1][1], a[1][2], a[1][3], kb[0][j], kb[1][j]);
            }
        }

        // ---- unshifted softmax (scale 1/8), partial row sums, P -> sP
#pragma unroll
        for (int mt = 0; mt < 2; mt++) {
            float rs0 = 0.f, rs1 = 0.f;
            const int r = rb + mt * 16 + grp;
#pragma unroll
            for (int j = 0; j < 4; j++) {
                sa[mt][j][0] = __expf(sa[mt][j][0] * 0.125f);
                sa[mt][j][1] = __expf(sa[mt][j][1] * 0.125f);
                sa[mt][j][2] = __expf(sa[mt][j][2] * 0.125f);
                sa[mt][j][3] = __expf(sa[mt][j][3] * 0.125f);
                rs0 += sa[mt][j][0] + sa[mt][j][1];
                rs1 += sa[mt][j][2] + sa[mt][j][3];
                int sc = (ch * 4 + j) * 8 + 2 * tig;
                *(uint2*)&sP[r * 64 + (sc ^ xp)] =
                    make_uint2(__float_as_uint(sa[mt][j][0]), __float_as_uint(sa[mt][j][1]));
                *(uint2*)&sP[(r + 8) * 64 + (sc ^ xp)] =
                    make_uint2(__float_as_uint(sa[mt][j][2]), __float_as_uint(sa[mt][j][3]));
            }
            rs0 += __shfl_xor_sync(~0u, rs0, 1); rs0 += __shfl_xor_sync(~0u, rs0, 2);
            rs1 += __shfl_xor_sync(~0u, rs1, 1); rs1 += __shfl_xor_sync(~0u, rs1, 2);
            l[mt][0] += rs0;
            l[mt][1] += rs1;
        }
        __syncwarp();  // sP region is warp-local

        // ---- O += P_half * V_half-rows  (k over warp's 32 s-values)
#pragma unroll
        for (int ksl = 0; ksl < 4; ksl++) {
            const int k0g = ch * 32 + ksl * 8;
            unsigned a[2][4];
#pragma unroll
            for (int mt = 0; mt < 2; mt++) {
                const int r = rb + mt * 16 + grp;
                a[mt][0] = sP[r * 64 + ((k0g + tig) ^ xp)];
                a[mt][1] = sP[(r + 8) * 64 + ((k0g + tig) ^ xp)];
                a[mt][2] = sP[r * 64 + ((k0g + tig + 4) ^ xp)];
                a[mt][3] = sP[(r + 8) * 64 + ((k0g + tig + 4) ^ xp)];
            }
            unsigned vb[2][2][4];
#pragma unroll
            for (int h = 0; h < 2; h++) {
                int row = k0g + tig + 4 * h;
                *(uint4*)vb[h][0] = *(const uint4*)&sV[row * 64 + (pb0 ^ xk)];
                *(uint4*)vb[h][1] = *(const uint4*)&sV[row * 64 + (pb1 ^ xk)];
            }
#pragma unroll
            for (int nt = 0; nt < 8; nt++) {
                mma8(o[0][nt], a[0][0], a[0][1], a[0][2], a[0][3],
                     vb[0][nt >> 2][nt & 3], vb[1][nt >> 2][nt & 3]);
                mma8(o[1][nt], a[1][0], a[1][1], a[1][2], a[1][3],
                     vb[0][nt >> 2][nt & 3], vb[1][nt >> 2][nt & 3]);
            }
        }
        __syncthreads();  // all warps done with sKT/sV/sP before next overwrite
    }

    // ---- epilogue: reduce O and l across the ch-pair, write transposed out
    // each warp stores the OTHER half's partial O (disjoint columns, same rows)
    if (ch == 0) {
#pragma unroll
        for (int mt = 0; mt < 2; mt++) {
            const int r = rb + mt * 16 + grp;
#pragma unroll
            for (int j = 0; j < 4; j++) {
                int c = (4 + j) * 8 + 2 * tig;
                *(uint2*)&sP[r * 64 + (c ^ xp)] =
                    make_uint2(__float_as_uint(o[mt][4 + j][0]), __float_as_uint(o[mt][4 + j][1]));
                *(uint2*)&sP[(r + 8) * 64 + (c ^ xp)] =
                    make_uint2(__float_as_uint(o[mt][4 + j][2]), __float_as_uint(o[mt][4 + j][3]));
            }
        }
    } else {
#pragma unroll
        for (int mt = 0; mt < 2; mt++) {
            const int r = rb + mt * 16 + grp;
#pragma unroll
            for (int j = 0; j < 4; j++) {
                int c = j * 8 + 2 * tig;
                *(uint2*)&sP[r * 64 + (c ^ xp)] =
                    make_uint2(__float_as_uint(o[mt][j][0]), __float_as_uint(o[mt][j][1]));
                *(uint2*)&sP[(r + 8) * 64 + (c ^ xp)] =
                    make_uint2(__float_as_uint(o[mt][j][2]), __float_as_uint(o[mt][j][3]));
            }
        }
    }
    // l partials -> sKT[ch*128 + row]
    if (tig == 0) {
#pragma unroll
        for (int mt = 0; mt < 2; mt++) {
            sKT[ch * 128 + rb + mt * 16 + grp]     = __float_as_uint(l[mt][0]);
            sKT[ch * 128 + rb + mt * 16 + grp + 8] = __float_as_uint(l[mt][1]);
        }
    }
    __syncthreads();

    float* ob = out + ((size_t)b * DD + hh * DH) * TT;
#pragma unroll
    for (int mt = 0; mt < 2; mt++) {
        const int r = rb + mt * 16 + grp;
        const float lp0 = __uint_as_float(sKT[(1 - ch) * 128 + r]);
        const float lp1 = __uint_as_float(sKT[(1 - ch) * 128 + r + 8]);
        const float ilo = 1.f / (l[mt][0] + lp0);
        const float ihi = 1.f / (l[mt][1] + lp1);
        const int rglo = t0 + r, rghi = rglo + 8;
        if (ch == 0) {
#pragma unroll
            for (int j = 0; j < 4; j++) {
                int c = j * 8 + 2 * tig;
                uint2 plo = *(const uint2*)&sP[r * 64 + (c ^ xp)];
                uint2 phi = *(const uint2*)&sP[(r + 8) * 64 + (c ^ xp)];
                ob[(size_t)c * TT + rglo]       = (o[mt][j][0] + __uint_as_float(plo.x)) * ilo;
                ob[(size_t)(c + 1) * TT + rglo] = (o[mt][j][1] + __uint_as_float(plo.y)) * ilo;
                ob[(size_t)c * TT + rghi]       = (o[mt][j][2] + __uint_as_float(phi.x)) * ihi;
                ob[(size_t)(c + 1) * TT + rghi] = (o[mt][j][3] + __uint_as_float(phi.y)) * ihi;
            }
        } else {
#pragma unroll
            for (int j = 0; j < 4; j++) {
                int c = (4 + j) * 8 + 2 * tig;
                uint2 plo = *(const uint2*)&sP[r * 64 + (c ^ xp)];
                uint2 phi = *(const uint2*)&sP[(r + 8) * 64 + (c ^ xp)];
                ob[(size_t)c * TT + rglo]       = (o[mt][4 + j][0] + __uint_as_float(plo.x)) * ilo;
                ob[(size_t)(c + 1) * TT + rglo] = (o[mt][4 + j][1] + __uint_as_float(plo.y)) * ilo;
                ob[(size_t)c * TT + rghi]       = (o[mt][4 + j][2] + __uint_as_float(phi.x)) * ihi;
                ob[(size_t)(c + 1) * TT + rghi] = (o[mt][4 + j][3] + __uint_as_float(phi.y)) * ihi;
            }
        }
    }
}

extern "C" void kernel_launch(void* const* d_in, const int* in_sizes, int n_in,
                              void* d_out, int out_size) {
    (void)in_sizes; (void)n_in; (void)out_size;
    const float* x   = (const float*)d_in[0];   // [4,1024,2048] fp32
    const float* qkv = (const float*)d_in[1];   // [3,16,1024,64] fp32
    float* out = (float*)d_out;                 // [4,1024,2048] fp32

    qkv_proj_kernel<<<dim3(TT / 256, 3 * BSZ * NH), 256>>>(x, qkv);

    const int smem2 = SMEM2_WORDS * 4;  // 100352 B -> 2 blocks/SM
    cudaFuncSetAttribute(attn_kernel, cudaFuncAttributeMaxDynamicSharedMemorySize, smem2);
    attn_kernel<<<dim3(TT / 128, BSZ * NH), 256, smem2>>>(out);
}